// round 7
// baseline (speedup 1.0000x reference)
#include <cuda_runtime.h>
#include <cstdint>

#define NTHR 320
#define GROUP 16
#define ALPHA 0.2f
#define BN_EPS 1e-5f

// ---- smem layout ----
// A1: [160 rows][132 f32 words, swizzled] = 84480 B   (dead after GEMM1)
// dump1 [160][72] f32 = 46080 B  @ 0      (aliases A1)
// A2   [160][68 swizzled] f32    @ 46080  (aliases A1 tail + beyond)
// dump2 [160][40] f32 = 25600 B  @ 0      (aliases dump1, dead after epi1)
#define OFF_A2 46080
#define SMEM_BYTES 89600
#define PITCH1 132
#define PITCH2 68
#define PD1 72
#define PD2 40

// ---- device-global prepared weights (tf32 bit patterns) ----
__device__ uint4  g_W1F[2304];   // [9 ntile][8 q][32 lane] {b0e,b1e,b0o,b1o}
__device__ uint4  g_W2F[640];    // [5][4][32]
__device__ float2 g_WLP[2080];   // [13 c][5 n][32 l]
__device__ float  g_CST[64];     // sc1@0 bi1@8 sc2@16 bi2@24 bl@32

// ------------- helpers -------------
__device__ __forceinline__ uint32_t f2tf32(float v) {
    uint32_t r; asm("cvt.rna.tf32.f32 %0, %1;" : "=r"(r) : "f"(v)); return r;
}
__device__ __forceinline__ void mma_tf32(float* d, const uint32_t* a, uint32_t b0, uint32_t b1) {
    asm volatile("mma.sync.aligned.m16n8k8.row.col.f32.tf32.tf32.f32 "
                 "{%0,%1,%2,%3},{%4,%5,%6,%7},{%8,%9},{%0,%1,%2,%3};"
                 : "+f"(d[0]), "+f"(d[1]), "+f"(d[2]), "+f"(d[3])
                 : "r"(a[0]), "r"(a[1]), "r"(a[2]), "r"(a[3]), "r"(b0), "r"(b1));
}
__device__ __forceinline__ float wred(float v) {
    #pragma unroll
    for (int s = 16; s > 0; s >>= 1) v += __shfl_xor_sync(0xffffffffu, v, s);
    return v;
}
template <int C>
__device__ __forceinline__ void attn_apply(const float s1[5], const float s2[5],
                                           const float (&h)[C][5], float (&o)[C][5]) {
    #pragma unroll
    for (int j = 0; j < 5; ++j) {
        float e[5]; float m = -1e30f;
        #pragma unroll
        for (int i = 0; i < 5; ++i) {
            float v = s1[i] + s2[j];
            v = v > 0.f ? v : ALPHA * v;
            e[i] = v; m = fmaxf(m, v);
        }
        float Z = 0.f;
        #pragma unroll
        for (int i = 0; i < 5; ++i) { e[i] = __expf(e[i] - m); Z += e[i]; }
        float rz = __fdividef(1.f, Z);
        #pragma unroll
        for (int i = 0; i < 5; ++i) {
            float wv = e[i] * rz;
            #pragma unroll
            for (int c = 0; c < C; ++c) o[c][i] = fmaf(wv, h[c][j], o[c][i]);
        }
    }
}

// dual-m-tile tf32 GEMM: A frags via swizzled LDS.128, B frags from global (L1-hot)
template<int NT, int NB, int NQ>
__device__ __forceinline__ void run_gemmM2(float (&acc)[2][NT][4], const uint4* __restrict__ WF,
                                           const float* r00, const float* r01,
                                           const float* r10, const float* r11, int l) {
    #pragma unroll
    for (int mm = 0; mm < 2; ++mm)
        #pragma unroll
        for (int t = 0; t < NT; ++t) { acc[mm][t][0]=0.f; acc[mm][t][1]=0.f; acc[mm][t][2]=0.f; acc[mm][t][3]=0.f; }
    #pragma unroll
    for (int q = 0; q < NQ; ++q) {
        const int off = (q >> 1) * 32 + (q & 1) * 4;
        uint4 u0 = *(const uint4*)(r00 + off);
        uint4 v0 = *(const uint4*)(r01 + off);
        uint4 u1 = *(const uint4*)(r10 + off);
        uint4 v1 = *(const uint4*)(r11 + off);
        uint32_t aE0[4] = {u0.x, v0.x, u0.y, v0.y};
        uint32_t aO0[4] = {u0.z, v0.z, u0.w, v0.w};
        uint32_t aE1[4] = {u1.x, v1.x, u1.y, v1.y};
        uint32_t aO1[4] = {u1.z, v1.z, u1.w, v1.w};
        #pragma unroll
        for (int t = 0; t < NT; ++t) {
            uint4 bf = WF[((NB + t) * NQ + q) * 32 + l];
            mma_tf32(acc[0][t], aE0, bf.x, bf.y);
            mma_tf32(acc[0][t], aO0, bf.z, bf.w);
            mma_tf32(acc[1][t], aE1, bf.x, bf.y);
            mma_tf32(acc[1][t], aO1, bf.z, bf.w);
        }
    }
}
template<int NT, int NB>
__device__ __forceinline__ void dump_accM2(const float (&acc)[2][NT][4], float* d, int pitch, int i_m, int l) {
    #pragma unroll
    for (int mm = 0; mm < 2; ++mm) {
        int rb = (i_m + 5 * mm) * 16 + (l >> 2);
        #pragma unroll
        for (int t = 0; t < NT; ++t) {
            int c = (NB + t) * 8 + (l & 3) * 2;
            *(float2*)(d + rb * pitch + c)       = make_float2(acc[mm][t][0], acc[mm][t][1]);
            *(float2*)(d + (rb + 8) * pitch + c) = make_float2(acc[mm][t][2], acc[mm][t][3]);
        }
    }
}

// ================= single merged prep kernel (1 block, 1024 threads) =================
__global__ void __launch_bounds__(1024, 1)
prep(const float* __restrict__ Wt1, const float* __restrict__ a11, const float* __restrict__ a21,
     const float* __restrict__ Wt2, const float* __restrict__ a12, const float* __restrict__ a22,
     const float* __restrict__ Wl, const float* __restrict__ bl,
     const float* __restrict__ g1, const float* __restrict__ b1,
     const float* __restrict__ m1, const float* __restrict__ v1,
     const float* __restrict__ g2, const float* __restrict__ b2,
     const float* __restrict__ m2, const float* __restrict__ v2)
{
    __shared__ float s_score[512];
    const int t = threadIdx.x;

    if (t < 512) {
        int k = t >> 2, s = t & 3;
        float sa = 0.f, sb = 0.f;
        if (k < 125) {
            #pragma unroll 4
            for (int oo = 0; oo < 16; ++oo) {
                int o = s * 16 + oo;
                float wv = Wt1[o * 125 + k];
                sa = fmaf(a11[o], wv, sa); sb = fmaf(a21[o], wv, sb);
            }
        }
        sa += __shfl_xor_sync(0xffffffffu, sa, 1); sa += __shfl_xor_sync(0xffffffffu, sa, 2);
        sb += __shfl_xor_sync(0xffffffffu, sb, 1); sb += __shfl_xor_sync(0xffffffffu, sb, 2);
        if (s == 0) { s_score[k] = sa; s_score[128 + k] = sb; }
    } else if (t < 768) {
        int k = (t - 512) >> 2, s = t & 3;
        float sa = 0.f, sb = 0.f;
        #pragma unroll
        for (int oo = 0; oo < 8; ++oo) {
            int o = s * 8 + oo;
            float wv = Wt2[o * 64 + k];
            sa = fmaf(a12[o], wv, sa); sb = fmaf(a22[o], wv, sb);
        }
        sa += __shfl_xor_sync(0xffffffffu, sa, 1); sa += __shfl_xor_sync(0xffffffffu, sa, 2);
        sb += __shfl_xor_sync(0xffffffffu, sb, 1); sb += __shfl_xor_sync(0xffffffffu, sb, 2);
        if (s == 0) { s_score[256 + k] = sa; s_score[384 + k] = sb; }
    } else if (t >= 800 && t < 805) {
        int i = t - 800;
        float s = g1[i] * rsqrtf(v1[i] + BN_EPS);
        g_CST[i] = s; g_CST[8 + i] = b1[i] - m1[i] * s;
    } else if (t >= 805 && t < 810) {
        int i = t - 805;
        float s = g2[i] * rsqrtf(v2[i] + BN_EPS);
        g_CST[16 + i] = s; g_CST[24 + i] = b2[i] - m2[i] * s;
    } else if (t >= 810 && t < 823) {
        g_CST[32 + (t - 810)] = bl[t - 810];
    }
    for (int e = t; e < 2080; e += 1024) {
        int c = e / 160, rem = e - c * 160;
        int n = rem >> 5, l = rem & 31;
        g_WLP[e] = make_float2(Wl[c * 320 + n * 64 + l], Wl[c * 320 + n * 64 + 32 + l]);
    }
    __syncthreads();

    for (int e = t; e < 2304; e += 1024) {
        int T = e >> 8, q = (e >> 5) & 7, L = e & 31;
        int g = L >> 2, tt = L & 3;
        int nn = T * 8 + g;
        uint32_t v[4];
        #pragma unroll
        for (int i = 0; i < 4; ++i) {
            int k = 16 * q + (i >> 1) * 8 + (i & 1) * 4 + tt;
            float vv = 0.f;
            if (k < 125) {
                if (nn < 64)      vv = Wt1[nn * 125 + k];
                else if (nn == 64) vv = s_score[k];
                else if (nn == 65) vv = s_score[128 + k];
            }
            v[i] = f2tf32(vv);
        }
        g_W1F[e] = make_uint4(v[0], v[1], v[2], v[3]);
    }
    for (int f = t; f < 640; f += 1024) {
        int T = f >> 7, q = (f >> 5) & 3, L = f & 31;
        int g = L >> 2, tt = L & 3;
        int nn = T * 8 + g;
        uint32_t v[4];
        #pragma unroll
        for (int i = 0; i < 4; ++i) {
            int k = 16 * q + (i >> 1) * 8 + (i & 1) * 4 + tt;
            float vv = 0.f;
            if (nn < 32)      vv = Wt2[nn * 64 + k];
            else if (nn == 32) vv = s_score[256 + k];
            else if (nn == 33) vv = s_score[384 + k];
            v[i] = f2tf32(vv);
        }
        g_W2F[f] = make_uint4(v[0], v[1], v[2], v[3]);
    }
}

// ================= main fused kernel =================
__global__ void __launch_bounds__(NTHR, 2)
gat7_kernel(const float* __restrict__ x, float* __restrict__ out, int B)
{
    extern __shared__ __align__(16) char smc[];
    const int tid = threadIdx.x;
    const int w = tid >> 5, l = tid & 31;
    const int b0 = blockIdx.x * GROUP;
    float* A1 = (float*)smc;
    float* A2 = (float*)(smc + OFF_A2);

    // ---- stage x -> A1 (tf32, swizzled rows; 4 coalesced LDG + 4 CF STS per row) ----
    {
        const int pp = w / 5, nn = w - 5 * pp;       // row-in-batch = w
        const float* xrow = x + (size_t)b0 * 1250 + nn * 250 + pp * 125;
        const int P = ((l >> 4) + 2 * (l & 3)) * 4 + ((l >> 2) & 3);
        #pragma unroll 4
        for (int j = 0; j < GROUP; ++j) {
            const float* src = xrow + (size_t)j * 1250;
            bool bv = (b0 + j) < B;
            float* arow = A1 + (j * 10 + w) * PITCH1;
            #pragma unroll
            for (int iv = 0; iv < 4; ++iv) {
                int k = l + 32 * iv;
                float v = (bv && k < 125) ? src[k] : 0.f;
                *(uint32_t*)(arow + 32 * iv + P) = f2tf32(v);
            }
        }
    }
    __syncthreads();

    const int i_m = w % 5, j_n = w / 5;
    const int g = l >> 2, tt = l & 3;
    float* d1 = A1;

    // ---- GEMM1: A[160x128] x W1frag[72x128] -> dump1 [160][72] ----
    {
        const float* r00 = A1 + (i_m * 16 + g) * PITCH1 + 8 * tt;
        const float* r01 = r00 + 8 * PITCH1;
        const float* r10 = A1 + ((i_m + 5) * 16 + g) * PITCH1 + 8 * tt;
        const float* r11 = r10 + 8 * PITCH1;
        if (j_n == 0) {
            float acc[2][5][4];
            run_gemmM2<5, 0, 8>(acc, g_W1F, r00, r01, r10, r11, l);
            __syncthreads();
            dump_accM2<5, 0>(acc, d1, PD1, i_m, l);
        } else {
            float acc[2][4][4];
            run_gemmM2<4, 5, 8>(acc, g_W1F, r00, r01, r10, r11, l);
            __syncthreads();
            dump_accM2<4, 5>(acc, d1, PD1, i_m, l);
        }
    }
    __syncthreads();

    // ---- epilogue 1: attention + BN + ReLU -> A2 (swizzled tf32) ----
    {
        float sc1[5], bi1[5];
        #pragma unroll
        for (int n = 0; n < 5; ++n) { sc1[n] = g_CST[n]; bi1[n] = g_CST[8 + n]; }
        const int q2 = l >> 3;
        const int w0 = (q2 >> 1) * 32 + ((q2 & 1) + ((2 * l) & 3) * 2) * 4 + ((l >> 1) & 3);
        for (int u = w; u < 2 * GROUP; u += 10) {
            int lb = u >> 1, p = u & 1;
            int rb = lb * 10 + p * 5;
            float h12[2][5], s1[5], s2[5];
            #pragma unroll
            for (int n = 0; n < 5; ++n) {
                float2 hv = *(const float2*)(d1 + (rb + n) * PD1 + 2 * l);
                h12[0][n] = hv.x; h12[1][n] = hv.y;
                float2 sv = *(const float2*)(d1 + (rb + n) * PD1 + 64);
                s1[n] = sv.x; s2[n] = sv.y;
            }
            float o12[2][5];
            #pragma unroll
            for (int n = 0; n < 5; ++n) { o12[0][n] = 0.f; o12[1][n] = 0.f; }
            attn_apply<2>(s1, s2, h12, o12);
            #pragma unroll
            for (int n = 0; n < 5; ++n) {
                float y0 = fmaxf(fmaf(o12[0][n], sc1[n], bi1[n]), 0.f);
                float y1 = fmaxf(fmaf(o12[1][n], sc1[n], bi1[n]), 0.f);
                float* arow = A2 + (rb + n) * PITCH2;
                *(uint32_t*)(arow + w0)     = f2tf32(y0);
                *(uint32_t*)(arow + w0 + 8) = f2tf32(y1);
            }
        }
    }
    __syncthreads();

    // ---- GEMM2: A2[160x64] x W2frag[40x64] -> dump2 [160][40] @ region0 ----
    float* d2 = A1;
    {
        const float* r00 = A2 + (i_m * 16 + g) * PITCH2 + 8 * tt;
        const float* r01 = r00 + 8 * PITCH2;
        const float* r10 = A2 + ((i_m + 5) * 16 + g) * PITCH2 + 8 * tt;
        const float* r11 = r10 + 8 * PITCH2;
        if (j_n == 0) {
            float acc[2][3][4];
            run_gemmM2<3, 0, 4>(acc, g_W2F, r00, r01, r10, r11, l);
            dump_accM2<3, 0>(acc, d2, PD2, i_m, l);
        } else {
            float acc[2][2][4];
            run_gemmM2<2, 3, 4>(acc, g_W2F, r00, r01, r10, r11, l);
            dump_accM2<2, 3>(acc, d2, PD2, i_m, l);
        }
    }
    __syncthreads();

    // ---- epilogue 2: cross attention + BN + final linear ----
    {
        float sc2v[5], bi2v[5];
        #pragma unroll
        for (int n = 0; n < 5; ++n) { sc2v[n] = g_CST[16 + n]; bi2v[n] = g_CST[24 + n]; }
        for (int u = w; u < GROUP; u += 10) {
            int bb = b0 + u;
            int rA = u * 10, rN = rA + 5;
            float hA[1][5], hN[1][5];
            float s1a[5], s2a[5], s1b[5], s2b[5];
            #pragma unroll
            for (int n = 0; n < 5; ++n) {
                hA[0][n] = d2[(rA + n) * PD2 + l];
                hN[0][n] = d2[(rN + n) * PD2 + l];
                float2 sA = *(const float2*)(d2 + (rA + n) * PD2 + 32);
                float2 sN = *(const float2*)(d2 + (rN + n) * PD2 + 32);
                s1a[n] = sA.x; s2b[n] = sA.y;
                s1b[n] = sN.x; s2a[n] = sN.y;
            }
            float oA[1][5], oN[1][5];
            #pragma unroll
            for (int n = 0; n < 5; ++n) { oA[0][n] = 0.f; oN[0][n] = 0.f; }
            attn_apply<1>(s1a, s2a, hA, oA);
            attn_apply<1>(s1b, s2b, hN, oN);
            float fa[5], fb[5];
            #pragma unroll
            for (int n = 0; n < 5; ++n) {
                fa[n] = fmaxf(fmaf(oA[0][n], sc2v[n], bi2v[n]), 0.f);
                fb[n] = fmaxf(fmaf(oN[0][n], sc2v[n], bi2v[n]), 0.f);
            }
            float acc13[13];
            #pragma unroll
            for (int c = 0; c < 13; ++c) acc13[c] = 0.f;
            #pragma unroll
            for (int n = 0; n < 5; ++n) {
                #pragma unroll
                for (int c = 0; c < 13; ++c) {
                    float2 wp = g_WLP[(c * 5 + n) * 32 + l];
                    acc13[c] += fa[n] * wp.x + fb[n] * wp.y;
                }
            }
            #pragma unroll
            for (int c = 0; c < 13; ++c) acc13[c] = wred(acc13[c]);
            if (l < 13 && bb < B) {
                float ov = 0.f;
                #pragma unroll
                for (int c = 0; c < 13; ++c) if (l == c) ov = acc13[c];
                out[(size_t)bb * 13 + l] = ov + g_CST[32 + l];
            }
        }
    }
}

extern "C" void kernel_launch(void* const* d_in, const int* in_sizes, int n_in,
                              void* d_out, int out_size)
{
    const float* x   = (const float*)d_in[0];
    const float* Wt1 = (const float*)d_in[1];
    const float* a11 = (const float*)d_in[2];
    const float* a21 = (const float*)d_in[3];
    const float* g1  = (const float*)d_in[4];
    const float* b1  = (const float*)d_in[5];
    const float* m1  = (const float*)d_in[6];
    const float* v1  = (const float*)d_in[7];
    const float* Wt2 = (const float*)d_in[8];
    const float* a12 = (const float*)d_in[9];
    const float* a22 = (const float*)d_in[10];
    const float* g2  = (const float*)d_in[11];
    const float* b2  = (const float*)d_in[12];
    const float* m2  = (const float*)d_in[13];
    const float* v2  = (const float*)d_in[14];
    const float* Wl  = (const float*)d_in[15];
    const float* bl  = (const float*)d_in[16];

    int B = in_sizes[0] / 1250;
    prep<<<1, 1024>>>(Wt1, a11, a21, Wt2, a12, a22, Wl, bl,
                      g1, b1, m1, v1, g2, b2, m2, v2);
    int grid = (B + GROUP - 1) / GROUP;
    cudaFuncSetAttribute(gat7_kernel, cudaFuncAttributeMaxDynamicSharedMemorySize, SMEM_BYTES);
    cudaFuncSetAttribute(gat7_kernel, cudaFuncAttributePreferredSharedMemoryCarveout, 100);
    gat7_kernel<<<grid, NTHR, SMEM_BYTES>>>(x, (float*)d_out, B);
}

// round 8
// speedup vs baseline: 1.3838x; 1.3838x over previous
#include <cuda_runtime.h>
#include <cstdint>

#define NTHR 320
#define GROUP 8
#define ALPHA 0.2f
#define BN_EPS 1e-5f

// ---- smem layout ----
// A1: [80 rows][160 f32 words, chunk-swizzled] = 51200 B (dead after GEMM1)
// dump1 [80][72] f32 = 23040 B @ 0          (aliases A1)
// A2   [80][96 words, swizzled] = 30720 B @ 23040 (aliases dead A1 tail)
// dump2 [80][40] f32 = 12800 B @ 0          (aliases dump1)
#define PITCH1 160
#define PITCH2 96
#define OFF_A2 23040
#define SMEM_BYTES 53760
#define PD1 72
#define PD2 40

// ---- device-global prepared weights (tf32 bit patterns) ----
__device__ uint4  g_W1F[2304];   // [9 ntile][8 qpair][32 lane] = W[nn][16q+4tt .. +3]
__device__ uint4  g_W2F[640];    // [5][4][32]
__device__ float2 g_WLP[2080];   // [13 c][5 n][32 l]
__device__ float  g_CST[64];     // sc1@0 bi1@8 sc2@16 bi2@24 bl@32

// ------------- helpers -------------
__device__ __forceinline__ uint32_t f2tf32(float v) {
    uint32_t r; asm("cvt.rna.tf32.f32 %0, %1;" : "=r"(r) : "f"(v)); return r;
}
__device__ __forceinline__ void mma_tf32(float* d, const uint32_t* a, uint32_t b0, uint32_t b1) {
    asm volatile("mma.sync.aligned.m16n8k8.row.col.f32.tf32.tf32.f32 "
                 "{%0,%1,%2,%3},{%4,%5,%6,%7},{%8,%9},{%0,%1,%2,%3};"
                 : "+f"(d[0]), "+f"(d[1]), "+f"(d[2]), "+f"(d[3])
                 : "r"(a[0]), "r"(a[1]), "r"(a[2]), "r"(a[3]), "r"(b0), "r"(b1));
}
__device__ __forceinline__ float wred(float v) {
    #pragma unroll
    for (int s = 16; s > 0; s >>= 1) v += __shfl_xor_sync(0xffffffffu, v, s);
    return v;
}
template <int C>
__device__ __forceinline__ void attn_apply(const float s1[5], const float s2[5],
                                           const float (&h)[C][5], float (&o)[C][5]) {
    #pragma unroll
    for (int j = 0; j < 5; ++j) {
        float e[5]; float m = -1e30f;
        #pragma unroll
        for (int i = 0; i < 5; ++i) {
            float v = s1[i] + s2[j];
            v = v > 0.f ? v : ALPHA * v;
            e[i] = v; m = fmaxf(m, v);
        }
        float Z = 0.f;
        #pragma unroll
        for (int i = 0; i < 5; ++i) { e[i] = __expf(e[i] - m); Z += e[i]; }
        float rz = __fdividef(1.f, Z);
        #pragma unroll
        for (int i = 0; i < 5; ++i) {
            float wv = e[i] * rz;
            #pragma unroll
            for (int c = 0; c < C; ++c) o[c][i] = fmaf(wv, h[c][j], o[c][i]);
        }
    }
}

// tf32 GEMM: A frags via one LDS.128 per row per q-pair (swizzled), B frags from global (L1-hot)
// p0/p1 = smem row base (rows g, g+8 of this m-tile) + 4*tt words; xb = g&1 (swizzle bit)
template<int NT, int NB, int NQ>
__device__ __forceinline__ void run_gemm(float (&acc)[NT][4], const uint4* __restrict__ WF,
                                         const float* p0, const float* p1, int xb, int l) {
    #pragma unroll
    for (int t = 0; t < NT; ++t) { acc[t][0]=0.f; acc[t][1]=0.f; acc[t][2]=0.f; acc[t][3]=0.f; }
    #pragma unroll
    for (int q = 0; q < NQ; ++q) {
        const int off = 16 * (q ^ xb);
        uint4 u0 = *(const uint4*)(p0 + off);
        uint4 v0 = *(const uint4*)(p1 + off);
        uint32_t aE[4] = {u0.x, v0.x, u0.y, v0.y};
        uint32_t aO[4] = {u0.z, v0.z, u0.w, v0.w};
        #pragma unroll
        for (int t = 0; t < NT; ++t) {
            uint4 bf = WF[((NB + t) * NQ + q) * 32 + l];
            mma_tf32(acc[t], aE, bf.x, bf.y);
            mma_tf32(acc[t], aO, bf.z, bf.w);
        }
    }
}
template<int NT, int NB>
__device__ __forceinline__ void dump_acc(const float (&acc)[NT][4], float* d, int pitch, int i_m, int l) {
    int rb = i_m * 16 + (l >> 2);
    #pragma unroll
    for (int t = 0; t < NT; ++t) {
        int c = (NB + t) * 8 + (l & 3) * 2;
        *(float2*)(d + rb * pitch + c)       = make_float2(acc[t][0], acc[t][1]);
        *(float2*)(d + (rb + 8) * pitch + c) = make_float2(acc[t][2], acc[t][3]);
    }
}

// ================= single merged prep kernel (1 block, 1024 threads) =================
__global__ void __launch_bounds__(1024, 1)
prep(const float* __restrict__ Wt1, const float* __restrict__ a11, const float* __restrict__ a21,
     const float* __restrict__ Wt2, const float* __restrict__ a12, const float* __restrict__ a22,
     const float* __restrict__ Wl, const float* __restrict__ bl,
     const float* __restrict__ g1, const float* __restrict__ b1,
     const float* __restrict__ m1, const float* __restrict__ v1,
     const float* __restrict__ g2, const float* __restrict__ b2,
     const float* __restrict__ m2, const float* __restrict__ v2)
{
    __shared__ float s_score[512];   // w1a[0..127] w1b[128..255] w2a[256..319] w2b[384..447]
    const int t = threadIdx.x;

    if (t < 512) {
        int k = t >> 2, s = t & 3;
        float sa = 0.f, sb = 0.f;
        if (k < 125) {
            #pragma unroll 4
            for (int oo = 0; oo < 16; ++oo) {
                int o = s * 16 + oo;
                float wv = Wt1[o * 125 + k];
                sa = fmaf(a11[o], wv, sa); sb = fmaf(a21[o], wv, sb);
            }
        }
        sa += __shfl_xor_sync(0xffffffffu, sa, 1); sa += __shfl_xor_sync(0xffffffffu, sa, 2);
        sb += __shfl_xor_sync(0xffffffffu, sb, 1); sb += __shfl_xor_sync(0xffffffffu, sb, 2);
        if (s == 0) { s_score[k] = sa; s_score[128 + k] = sb; }
    } else if (t < 768) {
        int k = (t - 512) >> 2, s = t & 3;
        float sa = 0.f, sb = 0.f;
        #pragma unroll
        for (int oo = 0; oo < 8; ++oo) {
            int o = s * 8 + oo;
            float wv = Wt2[o * 64 + k];
            sa = fmaf(a12[o], wv, sa); sb = fmaf(a22[o], wv, sb);
        }
        sa += __shfl_xor_sync(0xffffffffu, sa, 1); sa += __shfl_xor_sync(0xffffffffu, sa, 2);
        sb += __shfl_xor_sync(0xffffffffu, sb, 1); sb += __shfl_xor_sync(0xffffffffu, sb, 2);
        if (s == 0) { s_score[256 + k] = sa; s_score[384 + k] = sb; }
    } else if (t >= 800 && t < 805) {
        int i = t - 800;
        float s = g1[i] * rsqrtf(v1[i] + BN_EPS);
        g_CST[i] = s; g_CST[8 + i] = b1[i] - m1[i] * s;
    } else if (t >= 805 && t < 810) {
        int i = t - 805;
        float s = g2[i] * rsqrtf(v2[i] + BN_EPS);
        g_CST[16 + i] = s; g_CST[24 + i] = b2[i] - m2[i] * s;
    } else if (t >= 810 && t < 823) {
        g_CST[32 + (t - 810)] = bl[t - 810];
    }
    for (int e = t; e < 2080; e += 1024) {
        int c = e / 160, rem = e - c * 160;
        int n = rem >> 5, l = rem & 31;
        g_WLP[e] = make_float2(Wl[c * 320 + n * 64 + l], Wl[c * 320 + n * 64 + 32 + l]);
    }
    __syncthreads();

    // W1 fragments: uint4 = W[nn][16q+4tt .. 16q+4tt+3] (contiguous k)
    for (int e = t; e < 2304; e += 1024) {
        int T = e >> 8, q = (e >> 5) & 7, L = e & 31;
        int tt = L & 3;
        int nn = T * 8 + (L >> 2);
        uint32_t v[4];
        #pragma unroll
        for (int i = 0; i < 4; ++i) {
            int k = 16 * q + 4 * tt + i;
            float vv = 0.f;
            if (k < 125) {
                if (nn < 64)      vv = Wt1[nn * 125 + k];
                else if (nn == 64) vv = s_score[k];
                else if (nn == 65) vv = s_score[128 + k];
            }
            v[i] = f2tf32(vv);
        }
        g_W1F[e] = make_uint4(v[0], v[1], v[2], v[3]);
    }
    for (int f = t; f < 640; f += 1024) {
        int T = f >> 7, q = (f >> 5) & 3, L = f & 31;
        int tt = L & 3;
        int nn = T * 8 + (L >> 2);
        uint32_t v[4];
        #pragma unroll
        for (int i = 0; i < 4; ++i) {
            int k = 16 * q + 4 * tt + i;
            float vv = 0.f;
            if (nn < 32)      vv = Wt2[nn * 64 + k];
            else if (nn == 32) vv = s_score[256 + k];
            else if (nn == 33) vv = s_score[384 + k];
            v[i] = f2tf32(vv);
        }
        g_W2F[f] = make_uint4(v[0], v[1], v[2], v[3]);
    }
}

// ================= main fused kernel =================
__global__ void __launch_bounds__(NTHR, 3)
gat8_kernel(const float* __restrict__ x, float* __restrict__ out, int B)
{
    extern __shared__ __align__(16) char smc[];
    const int tid = threadIdx.x;
    const int w = tid >> 5, l = tid & 31;
    const int b0 = blockIdx.x * GROUP;
    float* A1 = (float*)smc;
    float* A2 = (float*)(smc + OFF_A2);

    // ---- stage x -> A1 (tf32, chunk-swizzled: chunk c of row r at c ^ ((r&1)<<2)) ----
    {
        const int pp = w / 5, nn = w - 5 * pp;   // row-in-batch = w
        const float* xrow = x + (size_t)b0 * 1250 + nn * 250 + pp * 125;
        #pragma unroll
        for (int j = 0; j < GROUP; ++j) {
            const float* src = xrow + (size_t)j * 1250;
            bool bv = (b0 + j) < B;
            int r = j * 10 + w;
            float* arow = A1 + r * PITCH1;
            const int X = (r & 1) << 2;
            #pragma unroll
            for (int iv = 0; iv < 4; ++iv) {
                int k = l + 32 * iv;
                float v = (bv && k < 125) ? src[k] : 0.f;
                int c = (k >> 2) ^ X;
                *(uint32_t*)(arow + 4 * c + (k & 3)) = f2tf32(v);
            }
        }
    }
    __syncthreads();

    const int i_m = w % 5, j_n = w / 5;
    const int g = l >> 2, tt = l & 3;
    const int xb = g & 1;
    float* d1 = A1;

    // ---- GEMM1: A[80x128] x W1frag[72x128] -> dump1 [80][72] ----
    {
        const float* p0 = A1 + (i_m * 16 + g) * PITCH1 + 4 * tt;
        const float* p1 = p0 + 8 * PITCH1;
        if (j_n == 0) {
            float acc[5][4];
            run_gemm<5, 0, 8>(acc, g_W1F, p0, p1, xb, l);
            __syncthreads();
            dump_acc<5, 0>(acc, d1, PD1, i_m, l);
        } else {
            float acc[4][4];
            run_gemm<4, 5, 8>(acc, g_W1F, p0, p1, xb, l);
            __syncthreads();
            dump_acc<4, 5>(acc, d1, PD1, i_m, l);
        }
    }
    __syncthreads();

    // ---- epilogue 1: attention + BN + ReLU -> A2 (tf32, swizzled) ----
    {
        float sc1[5], bi1[5];
        #pragma unroll
        for (int n = 0; n < 5; ++n) { sc1[n] = g_CST[n]; bi1[n] = g_CST[8 + n]; }
        for (int u = w; u < 2 * GROUP; u += 10) {
            int lb = u >> 1, p = u & 1;
            int rb = lb * 10 + p * 5;
            float h12[2][5], s1[5], s2[5];
            #pragma unroll
            for (int n = 0; n < 5; ++n) {
                float2 hv = *(const float2*)(d1 + (rb + n) * PD1 + 2 * l);
                h12[0][n] = hv.x; h12[1][n] = hv.y;
                float2 sv = *(const float2*)(d1 + (rb + n) * PD1 + 64);
                s1[n] = sv.x; s2[n] = sv.y;
            }
            float o12[2][5];
            #pragma unroll
            for (int n = 0; n < 5; ++n) { o12[0][n] = 0.f; o12[1][n] = 0.f; }
            attn_apply<2>(s1, s2, h12, o12);
            #pragma unroll
            for (int n = 0; n < 5; ++n) {
                float y0 = fmaxf(fmaf(o12[0][n], sc1[n], bi1[n]), 0.f);
                float y1 = fmaxf(fmaf(o12[1][n], sc1[n], bi1[n]), 0.f);
                int r = rb + n;
                int wd = r * PITCH2 + 4 * ((l >> 1) ^ ((r & 1) << 2)) + 2 * (l & 1);
                *(uint2*)(A2 + wd) = make_uint2(f2tf32(y0), f2tf32(y1));
            }
        }
    }
    __syncthreads();

    // ---- GEMM2: A2[80x64] x W2frag[40x64] -> dump2 [80][40] @ region0 ----
    float* d2 = A1;
    {
        const float* p0 = A2 + (i_m * 16 + g) * PITCH2 + 4 * tt;
        const float* p1 = p0 + 8 * PITCH2;
        if (j_n == 0) {
            float acc[3][4];
            run_gemm<3, 0, 4>(acc, g_W2F, p0, p1, xb, l);
            dump_acc<3, 0>(acc, d2, PD2, i_m, l);
        } else {
            float acc[2][4];
            run_gemm<2, 3, 4>(acc, g_W2F, p0, p1, xb, l);
            dump_acc<2, 3>(acc, d2, PD2, i_m, l);
        }
    }
    __syncthreads();

    // ---- epilogue 2: cross attention + BN + final linear ----
    if (w < GROUP) {
        const int u = w;
        int bb = b0 + u;
        float sc2v[5], bi2v[5];
        #pragma unroll
        for (int n = 0; n < 5; ++n) { sc2v[n] = g_CST[16 + n]; bi2v[n] = g_CST[24 + n]; }
        int rA = u * 10, rN = rA + 5;
        float hA[1][5], hN[1][5];
        float s1a[5], s2a[5], s1b[5], s2b[5];
        #pragma unroll
        for (int n = 0; n < 5; ++n) {
            hA[0][n] = d2[(rA + n) * PD2 + l];
            hN[0][n] = d2[(rN + n) * PD2 + l];
            float2 sA = *(const float2*)(d2 + (rA + n) * PD2 + 32);  // (hA@a12, hA@a22)
            float2 sN = *(const float2*)(d2 + (rN + n) * PD2 + 32);  // (hN@a12, hN@a22)
            s1a[n] = sA.x; s2b[n] = sA.y;
            s1b[n] = sN.x; s2a[n] = sN.y;
        }
        float oA[1][5], oN[1][5];
        #pragma unroll
        for (int n = 0; n < 5; ++n) { oA[0][n] = 0.f; oN[0][n] = 0.f; }
        attn_apply<1>(s1a, s2a, hA, oA);
        attn_apply<1>(s1b, s2b, hN, oN);
        float fa[5], fb[5];
        #pragma unroll
        for (int n = 0; n < 5; ++n) {
            fa[n] = fmaxf(fmaf(oA[0][n], sc2v[n], bi2v[n]), 0.f);
            fb[n] = fmaxf(fmaf(oN[0][n], sc2v[n], bi2v[n]), 0.f);
        }
        float acc13[13];
        #pragma unroll
        for (int c = 0; c < 13; ++c) acc13[c] = 0.f;
        #pragma unroll
        for (int n = 0; n < 5; ++n) {
            #pragma unroll
            for (int c = 0; c < 13; ++c) {
                float2 wp = g_WLP[(c * 5 + n) * 32 + l];
                acc13[c] += fa[n] * wp.x + fb[n] * wp.y;
            }
        }
        #pragma unroll
        for (int c = 0; c < 13; ++c) acc13[c] = wred(acc13[c]);
        if (l < 13 && bb < B) {
            float ov = 0.f;
            #pragma unroll
            for (int c = 0; c < 13; ++c) if (l == c) ov = acc13[c];
            out[(size_t)bb * 13 + l] = ov + g_CST[32 + l];
        }
    }
}

extern "C" void kernel_launch(void* const* d_in, const int* in_sizes, int n_in,
                              void* d_out, int out_size)
{
    const float* x   = (const float*)d_in[0];
    const float* Wt1 = (const float*)d_in[1];
    const float* a11 = (const float*)d_in[2];
    const float* a21 = (const float*)d_in[3];
    const float* g1  = (const float*)d_in[4];
    const float* b1  = (const float*)d_in[5];
    const float* m1  = (const float*)d_in[6];
    const float* v1  = (const float*)d_in[7];
    const float* Wt2 = (const float*)d_in[8];
    const float* a12 = (const float*)d_in[9];
    const float* a22 = (const float*)d_in[10];
    const float* g2  = (const float*)d_in[11];
    const float* b2  = (const float*)d_in[12];
    const float* m2  = (const float*)d_in[13];
    const float* v2  = (const float*)d_in[14];
    const float* Wl  = (const float*)d_in[15];
    const float* bl  = (const float*)d_in[16];

    int B = in_sizes[0] / 1250;
    prep<<<1, 1024>>>(Wt1, a11, a21, Wt2, a12, a22, Wl, bl,
                      g1, b1, m1, v1, g2, b2, m2, v2);
    int grid = (B + GROUP - 1) / GROUP;
    cudaFuncSetAttribute(gat8_kernel, cudaFuncAttributeMaxDynamicSharedMemorySize, SMEM_BYTES);
    cudaFuncSetAttribute(gat8_kernel, cudaFuncAttributePreferredSharedMemoryCarveout, 100);
    gat8_kernel<<<grid, NTHR, SMEM_BYTES>>>(x, (float*)d_out, B);
}

// round 9
// speedup vs baseline: 1.4784x; 1.0683x over previous
#include <cuda_runtime.h>
#include <cstdint>

#define NTHR 320
#define GROUP 8
#define ALPHA 0.2f
#define BN_EPS 1e-5f

// ---- smem layout (bytes) ----
// A1 [80][132 f32] = 42240 @0 (dead after GEMM1 dump)
// dump1 [80][72] f32 = 23040 @0         (aliases A1)
// A2   [80][68] f32  = 21760 @23040     (aliases dead A1 tail)
// dump2 [80][40] f32 = 12800 @0         (aliases dump1, dead after epi1)
#define OFF_A2 23040
#define SMEM_BYTES 44800
#define PITCH1 132        // f32 words per A1 row
#define PITCH2 68         // f32 words per A2 row
#define PD1 72
#define PD2 40

// ---- device-global prepared weights (tf32 bit patterns) ----
__device__ uint4  g_W1F[2304];   // [9 ntile][8 q(k16)][32 lane] {b0e,b1e,b0o,b1o}
__device__ uint4  g_W2F[640];    // [5][4][32]
__device__ float2 g_WLP[2080];   // [13 c][5 n][32 l]
__device__ float  g_CST[64];     // sc1@0 bi1@8 sc2@16 bi2@24 bl@32

// ------------- helpers -------------
__device__ __forceinline__ uint32_t f2tf32(float v) {
    uint32_t r; asm("cvt.rna.tf32.f32 %0, %1;" : "=r"(r) : "f"(v)); return r;
}
__device__ __forceinline__ void mma_tf32(float* d, const uint32_t* a, uint32_t b0, uint32_t b1) {
    asm volatile("mma.sync.aligned.m16n8k8.row.col.f32.tf32.tf32.f32 "
                 "{%0,%1,%2,%3},{%4,%5,%6,%7},{%8,%9},{%0,%1,%2,%3};"
                 : "+f"(d[0]), "+f"(d[1]), "+f"(d[2]), "+f"(d[3])
                 : "r"(a[0]), "r"(a[1]), "r"(a[2]), "r"(a[3]), "r"(b0), "r"(b1));
}
__device__ __forceinline__ float wred(float v) {
    #pragma unroll
    for (int s = 16; s > 0; s >>= 1) v += __shfl_xor_sync(0xffffffffu, v, s);
    return v;
}
template <int C>
__device__ __forceinline__ void attn_apply(const float s1[5], const float s2[5],
                                           const float (&h)[C][5], float (&o)[C][5]) {
    #pragma unroll
    for (int j = 0; j < 5; ++j) {
        float e[5]; float m = -1e30f;
        #pragma unroll
        for (int i = 0; i < 5; ++i) {
            float v = s1[i] + s2[j];
            v = v > 0.f ? v : ALPHA * v;
            e[i] = v; m = fmaxf(m, v);
        }
        float Z = 0.f;
        #pragma unroll
        for (int i = 0; i < 5; ++i) { e[i] = __expf(e[i] - m); Z += e[i]; }
        float rz = __fdividef(1.f, Z);
        #pragma unroll
        for (int i = 0; i < 5; ++i) {
            float wv = e[i] * rz;
            #pragma unroll
            for (int c = 0; c < C; ++c) o[c][i] = fmaf(wv, h[c][j], o[c][i]);
        }
    }
}

// tf32 GEMM: A from smem rows (conflict-free LDS.32), B frags from global (L1-hot)
template<int NT, int NB, int NQ>
__device__ __forceinline__ void run_gemm(float (&acc)[NT][4], const uint4* __restrict__ WF,
                                         const float* __restrict__ p0, const float* __restrict__ p1,
                                         int l) {
    #pragma unroll
    for (int t = 0; t < NT; ++t) { acc[t][0]=0.f; acc[t][1]=0.f; acc[t][2]=0.f; acc[t][3]=0.f; }
    #pragma unroll
    for (int q = 0; q < NQ; ++q) {
        const int k0 = 16 * q;
        uint32_t aE[4], aO[4];
        aE[0] = __float_as_uint(p0[k0]);      aE[1] = __float_as_uint(p1[k0]);
        aE[2] = __float_as_uint(p0[k0 + 4]);  aE[3] = __float_as_uint(p1[k0 + 4]);
        aO[0] = __float_as_uint(p0[k0 + 8]);  aO[1] = __float_as_uint(p1[k0 + 8]);
        aO[2] = __float_as_uint(p0[k0 + 12]); aO[3] = __float_as_uint(p1[k0 + 12]);
        #pragma unroll
        for (int t = 0; t < NT; ++t) {
            uint4 bf = WF[((NB + t) * NQ + q) * 32 + l];
            mma_tf32(acc[t], aE, bf.x, bf.y);
            mma_tf32(acc[t], aO, bf.z, bf.w);
        }
    }
}
template<int NT, int NB>
__device__ __forceinline__ void dump_acc(const float (&acc)[NT][4], float* d, int pitch, int i_m, int l) {
    int rb = i_m * 16 + (l >> 2);
    #pragma unroll
    for (int t = 0; t < NT; ++t) {
        int c = (NB + t) * 8 + (l & 3) * 2;
        *(float2*)(d + rb * pitch + c)       = make_float2(acc[t][0], acc[t][1]);
        *(float2*)(d + (rb + 8) * pitch + c) = make_float2(acc[t][2], acc[t][3]);
    }
}

// ================= single merged prep kernel (1 block, 1024 threads) =================
__global__ void __launch_bounds__(1024, 1)
prep(const float* __restrict__ Wt1, const float* __restrict__ a11, const float* __restrict__ a21,
     const float* __restrict__ Wt2, const float* __restrict__ a12, const float* __restrict__ a22,
     const float* __restrict__ Wl, const float* __restrict__ bl,
     const float* __restrict__ g1, const float* __restrict__ b1,
     const float* __restrict__ m1, const float* __restrict__ v1,
     const float* __restrict__ g2, const float* __restrict__ b2,
     const float* __restrict__ m2, const float* __restrict__ v2)
{
    __shared__ float s_score[512];   // w1a[0..127] w1b[128..255] w2a[256..319] w2b[384..447]
    const int t = threadIdx.x;

    if (t < 512) {
        int k = t >> 2, s = t & 3;
        float sa = 0.f, sb = 0.f;
        if (k < 125) {
            #pragma unroll 4
            for (int oo = 0; oo < 16; ++oo) {
                int o = s * 16 + oo;
                float wv = Wt1[o * 125 + k];
                sa = fmaf(a11[o], wv, sa); sb = fmaf(a21[o], wv, sb);
            }
        }
        sa += __shfl_xor_sync(0xffffffffu, sa, 1); sa += __shfl_xor_sync(0xffffffffu, sa, 2);
        sb += __shfl_xor_sync(0xffffffffu, sb, 1); sb += __shfl_xor_sync(0xffffffffu, sb, 2);
        if (s == 0) { s_score[k] = sa; s_score[128 + k] = sb; }
    } else if (t < 768) {
        int k = (t - 512) >> 2, s = t & 3;
        float sa = 0.f, sb = 0.f;
        #pragma unroll
        for (int oo = 0; oo < 8; ++oo) {
            int o = s * 8 + oo;
            float wv = Wt2[o * 64 + k];
            sa = fmaf(a12[o], wv, sa); sb = fmaf(a22[o], wv, sb);
        }
        sa += __shfl_xor_sync(0xffffffffu, sa, 1); sa += __shfl_xor_sync(0xffffffffu, sa, 2);
        sb += __shfl_xor_sync(0xffffffffu, sb, 1); sb += __shfl_xor_sync(0xffffffffu, sb, 2);
        if (s == 0) { s_score[256 + k] = sa; s_score[384 + k] = sb; }
    } else if (t >= 800 && t < 805) {
        int i = t - 800;
        float s = g1[i] * rsqrtf(v1[i] + BN_EPS);
        g_CST[i] = s; g_CST[8 + i] = b1[i] - m1[i] * s;
    } else if (t >= 805 && t < 810) {
        int i = t - 805;
        float s = g2[i] * rsqrtf(v2[i] + BN_EPS);
        g_CST[16 + i] = s; g_CST[24 + i] = b2[i] - m2[i] * s;
    } else if (t >= 810 && t < 823) {
        g_CST[32 + (t - 810)] = bl[t - 810];
    }
    for (int e = t; e < 2080; e += 1024) {
        int c = e / 160, rem = e - c * 160;
        int n = rem >> 5, l = rem & 31;
        g_WLP[e] = make_float2(Wl[c * 320 + n * 64 + l], Wl[c * 320 + n * 64 + 32 + l]);
    }
    __syncthreads();

    for (int e = t; e < 2304; e += 1024) {
        int T = e >> 8, q = (e >> 5) & 7, L = e & 31;
        int g = L >> 2, tt = L & 3;
        int nn = T * 8 + g;
        uint32_t v[4];
        #pragma unroll
        for (int i = 0; i < 4; ++i) {
            int k = 16 * q + (i >> 1) * 8 + (i & 1) * 4 + tt;
            float vv = 0.f;
            if (k < 125) {
                if (nn < 64)      vv = Wt1[nn * 125 + k];
                else if (nn == 64) vv = s_score[k];
                else if (nn == 65) vv = s_score[128 + k];
            }
            v[i] = f2tf32(vv);
        }
        g_W1F[e] = make_uint4(v[0], v[1], v[2], v[3]);
    }
    for (int f = t; f < 640; f += 1024) {
        int T = f >> 7, q = (f >> 5) & 3, L = f & 31;
        int g = L >> 2, tt = L & 3;
        int nn = T * 8 + g;
        uint32_t v[4];
        #pragma unroll
        for (int i = 0; i < 4; ++i) {
            int k = 16 * q + (i >> 1) * 8 + (i & 1) * 4 + tt;
            float vv = 0.f;
            if (nn < 32)      vv = Wt2[nn * 64 + k];
            else if (nn == 32) vv = s_score[256 + k];
            else if (nn == 33) vv = s_score[384 + k];
            v[i] = f2tf32(vv);
        }
        g_W2F[f] = make_uint4(v[0], v[1], v[2], v[3]);
    }
}

// ================= main fused kernel =================
__global__ void __launch_bounds__(NTHR, 4)
gat9_kernel(const float* __restrict__ x, float* __restrict__ out, int B)
{
    extern __shared__ __align__(16) char smc[];
    const int tid = threadIdx.x;
    const int w = tid >> 5, l = tid & 31;
    const int b0 = blockIdx.x * GROUP;
    float* A1 = (float*)smc;
    float* A2 = (float*)(smc + OFF_A2);

    // ---- stage x -> A1 rows (tf32, row-major pitch 132, conflict-free) ----
    {
        const int pp = w / 5, nn = w - 5 * pp;   // row within batch = w
        const float* xrow = x + (size_t)b0 * 1250 + nn * 250 + pp * 125;
        #pragma unroll
        for (int j = 0; j < GROUP; ++j) {
            const float* src = xrow + (size_t)j * 1250;
            bool bv = (b0 + j) < B;
            float* arow = A1 + (j * 10 + w) * PITCH1;
            #pragma unroll
            for (int i = 0; i < 4; ++i) {
                int k = l + 32 * i;
                float v = (bv && k < 125) ? src[k] : 0.f;
                *(uint32_t*)(arow + k) = f2tf32(v);
            }
        }
    }
    __syncthreads();

    const int i_m = w % 5, j_n = w / 5;
    const int g = l >> 2, tt = l & 3;
    float* d1 = A1;                      // dump region aliases A1

    // ---- GEMM1: A[80x128] x W1frag[72x128] -> dump1 [80][72] ----
    {
        const float* p0 = A1 + (i_m * 16 + g) * PITCH1 + tt;
        const float* p1 = p0 + 8 * PITCH1;
        if (j_n == 0) {
            float acc[5][4];
            run_gemm<5, 0, 8>(acc, g_W1F, p0, p1, l);
            __syncthreads();
            dump_acc<5, 0>(acc, d1, PD1, i_m, l);
        } else {
            float acc[4][4];
            run_gemm<4, 5, 8>(acc, g_W1F, p0, p1, l);
            __syncthreads();
            dump_acc<4, 5>(acc, d1, PD1, i_m, l);
        }
    }
    __syncthreads();

    // ---- epilogue 1: attention + BN + ReLU -> A2 (tf32 rows) ----
    {
        float sc1[5], bi1[5];
        #pragma unroll
        for (int n = 0; n < 5; ++n) { sc1[n] = g_CST[n]; bi1[n] = g_CST[8 + n]; }
        for (int u = w; u < 2 * GROUP; u += 10) {
            int lb = u >> 1, p = u & 1;
            int rb = lb * 10 + p * 5;
            float h12[2][5], s1[5], s2[5];
            #pragma unroll
            for (int n = 0; n < 5; ++n) {
                float2 hv = *(const float2*)(d1 + (rb + n) * PD1 + 2 * l);
                h12[0][n] = hv.x; h12[1][n] = hv.y;
                float2 sv = *(const float2*)(d1 + (rb + n) * PD1 + 64);
                s1[n] = sv.x; s2[n] = sv.y;
            }
            float o12[2][5];
            #pragma unroll
            for (int n = 0; n < 5; ++n) { o12[0][n] = 0.f; o12[1][n] = 0.f; }
            attn_apply<2>(s1, s2, h12, o12);
            #pragma unroll
            for (int n = 0; n < 5; ++n) {
                float y0 = fmaxf(fmaf(o12[0][n], sc1[n], bi1[n]), 0.f);
                float y1 = fmaxf(fmaf(o12[1][n], sc1[n], bi1[n]), 0.f);
                uint2 pk = make_uint2(f2tf32(y0), f2tf32(y1));
                *(uint2*)(A2 + (rb + n) * PITCH2 + 2 * l) = pk;
            }
        }
    }
    __syncthreads();

    // ---- GEMM2: A2[80x64] x W2frag[40x64] -> dump2 [80][40] @ region0 ----
    float* d2 = A1;
    {
        const float* p0 = A2 + (i_m * 16 + g) * PITCH2 + tt;
        const float* p1 = p0 + 8 * PITCH2;
        if (j_n == 0) {
            float acc[3][4];
            run_gemm<3, 0, 4>(acc, g_W2F, p0, p1, l);
            dump_acc<3, 0>(acc, d2, PD2, i_m, l);
        } else {
            float acc[2][4];
            run_gemm<2, 3, 4>(acc, g_W2F, p0, p1, l);
            dump_acc<2, 3>(acc, d2, PD2, i_m, l);
        }
    }
    __syncthreads();

    // ---- epilogue 2: cross attention + BN + final linear ----
    if (w < GROUP) {
        const int u = w;
        int bb = b0 + u;
        float sc2v[5], bi2v[5];
        #pragma unroll
        for (int n = 0; n < 5; ++n) { sc2v[n] = g_CST[16 + n]; bi2v[n] = g_CST[24 + n]; }
        int rA = u * 10, rN = rA + 5;
        float hA[1][5], hN[1][5];
        float s1a[5], s2a[5], s1b[5], s2b[5];
        #pragma unroll
        for (int n = 0; n < 5; ++n) {
            hA[0][n] = d2[(rA + n) * PD2 + l];
            hN[0][n] = d2[(rN + n) * PD2 + l];
            float2 sA = *(const float2*)(d2 + (rA + n) * PD2 + 32);  // (hA@a12, hA@a22)
            float2 sN = *(const float2*)(d2 + (rN + n) * PD2 + 32);  // (hN@a12, hN@a22)
            s1a[n] = sA.x; s2b[n] = sA.y;
            s1b[n] = sN.x; s2a[n] = sN.y;
        }
        float oA[1][5], oN[1][5];
        #pragma unroll
        for (int n = 0; n < 5; ++n) { oA[0][n] = 0.f; oN[0][n] = 0.f; }
        attn_apply<1>(s1a, s2a, hA, oA);
        attn_apply<1>(s1b, s2b, hN, oN);
        float fa[5], fb[5];
        #pragma unroll
        for (int n = 0; n < 5; ++n) {
            fa[n] = fmaxf(fmaf(oA[0][n], sc2v[n], bi2v[n]), 0.f);
            fb[n] = fmaxf(fmaf(oN[0][n], sc2v[n], bi2v[n]), 0.f);
        }
        float acc13[13];
        #pragma unroll
        for (int c = 0; c < 13; ++c) acc13[c] = 0.f;
        #pragma unroll
        for (int n = 0; n < 5; ++n) {
            #pragma unroll
            for (int c = 0; c < 13; ++c) {
                float2 wp = g_WLP[(c * 5 + n) * 32 + l];
                acc13[c] += fa[n] * wp.x + fb[n] * wp.y;
            }
        }
        #pragma unroll
        for (int c = 0; c < 13; ++c) acc13[c] = wred(acc13[c]);
        if (l < 13 && bb < B) {
            float ov = 0.f;
            #pragma unroll
            for (int c = 0; c < 13; ++c) if (l == c) ov = acc13[c];
            out[(size_t)bb * 13 + l] = ov + g_CST[32 + l];
        }
    }
}

extern "C" void kernel_launch(void* const* d_in, const int* in_sizes, int n_in,
                              void* d_out, int out_size)
{
    const float* x   = (const float*)d_in[0];
    const float* Wt1 = (const float*)d_in[1];
    const float* a11 = (const float*)d_in[2];
    const float* a21 = (const float*)d_in[3];
    const float* g1  = (const float*)d_in[4];
    const float* b1  = (const float*)d_in[5];
    const float* m1  = (const float*)d_in[6];
    const float* v1  = (const float*)d_in[7];
    const float* Wt2 = (const float*)d_in[8];
    const float* a12 = (const float*)d_in[9];
    const float* a22 = (const float*)d_in[10];
    const float* g2  = (const float*)d_in[11];
    const float* b2  = (const float*)d_in[12];
    const float* m2  = (const float*)d_in[13];
    const float* v2  = (const float*)d_in[14];
    const float* Wl  = (const float*)d_in[15];
    const float* bl  = (const float*)d_in[16];

    int B = in_sizes[0] / 1250;
    prep<<<1, 1024>>>(Wt1, a11, a21, Wt2, a12, a22, Wl, bl,
                      g1, b1, m1, v1, g2, b2, m2, v2);
    int grid = (B + GROUP - 1) / GROUP;
    cudaFuncSetAttribute(gat9_kernel, cudaFuncAttributeMaxDynamicSharedMemorySize, SMEM_BYTES);
    cudaFuncSetAttribute(gat9_kernel, cudaFuncAttributePreferredSharedMemoryCarveout, 100);
    gat9_kernel<<<grid, NTHR, SMEM_BYTES>>>(x, (float*)d_out, B);
}

// round 10
// speedup vs baseline: 1.5918x; 1.0767x over previous
#include <cuda_runtime.h>
#include <cstdint>

#define NTHR 320
#define GROUP 8
#define ALPHA 0.2f
#define BN_EPS 1e-5f

// ---- smem layout (bytes) ----
// A1 [80][132 f32] = 42240 @0 (dead after GEMM1 dump)
// dump1 [80][72] f32 = 23040 @0         (aliases A1)
// A2   [80][68] f32  = 21760 @23040     (aliases dead A1 tail)
// dump2 [80][40] f32 = 12800 @0         (aliases dump1, dead after epi1)
#define OFF_A2 23040
#define SMEM_BYTES 44800
#define PITCH1 132
#define PITCH2 68
#define PD1 72
#define PD2 40

typedef unsigned long long u64;

// ---- device-global prepared weights ----
__device__ uint4  g_W1F[2304];   // [9 ntile][8 q(k16)][32 lane] {b0e,b1e,b0o,b1o} tf32
__device__ uint4  g_W2F[640];    // [5][4][32]
__device__ float4 g_WLP4[1040];  // [13 c][5 n][16 m] = {Wl[c][n64+2m], +1, Wl[c][n64+32+2m], +1}
__device__ float  g_CST[64];     // sc1@0 bi1@8 sc2@16 bi2@24 bl@32

// ------------- helpers -------------
__device__ __forceinline__ uint32_t f2tf32(float v) {
    uint32_t r; asm("cvt.rna.tf32.f32 %0, %1;" : "=r"(r) : "f"(v)); return r;
}
__device__ __forceinline__ void mma_tf32(float* d, const uint32_t* a, uint32_t b0, uint32_t b1) {
    asm volatile("mma.sync.aligned.m16n8k8.row.col.f32.tf32.tf32.f32 "
                 "{%0,%1,%2,%3},{%4,%5,%6,%7},{%8,%9},{%0,%1,%2,%3};"
                 : "+f"(d[0]), "+f"(d[1]), "+f"(d[2]), "+f"(d[3])
                 : "r"(a[0]), "r"(a[1]), "r"(a[2]), "r"(a[3]), "r"(b0), "r"(b1));
}
__device__ __forceinline__ u64 pk2(float a, float b) {
    u64 r; asm("mov.b64 %0, {%1, %2};" : "=l"(r) : "f"(a), "f"(b)); return r;
}
__device__ __forceinline__ float2 upk2(u64 v) {
    float2 r; asm("mov.b64 {%0, %1}, %2;" : "=f"(r.x), "=f"(r.y) : "l"(v)); return r;
}
__device__ __forceinline__ void fma2(u64& d, u64 a, u64 b) {
    asm("fma.rn.f32x2 %0, %1, %2, %3;" : "=l"(d) : "l"(a), "l"(b), "l"(d));
}
__device__ __forceinline__ float lrelu(float v) { return v > 0.f ? v : ALPHA * v; }

// tf32 GEMM: A from smem rows (conflict-free LDS.32), B frags from global (L1-hot)
template<int NT, int NB, int NQ>
__device__ __forceinline__ void run_gemm(float (&acc)[NT][4], const uint4* __restrict__ WF,
                                         const float* __restrict__ p0, const float* __restrict__ p1,
                                         int l) {
    #pragma unroll
    for (int t = 0; t < NT; ++t) { acc[t][0]=0.f; acc[t][1]=0.f; acc[t][2]=0.f; acc[t][3]=0.f; }
    #pragma unroll
    for (int q = 0; q < NQ; ++q) {
        const int k0 = 16 * q;
        uint32_t aE[4], aO[4];
        aE[0] = __float_as_uint(p0[k0]);      aE[1] = __float_as_uint(p1[k0]);
        aE[2] = __float_as_uint(p0[k0 + 4]);  aE[3] = __float_as_uint(p1[k0 + 4]);
        aO[0] = __float_as_uint(p0[k0 + 8]);  aO[1] = __float_as_uint(p1[k0 + 8]);
        aO[2] = __float_as_uint(p0[k0 + 12]); aO[3] = __float_as_uint(p1[k0 + 12]);
        #pragma unroll
        for (int t = 0; t < NT; ++t) {
            uint4 bf = WF[((NB + t) * NQ + q) * 32 + l];
            mma_tf32(acc[t], aE, bf.x, bf.y);
            mma_tf32(acc[t], aO, bf.z, bf.w);
        }
    }
}
template<int NT, int NB>
__device__ __forceinline__ void dump_acc(const float (&acc)[NT][4], float* d, int pitch, int i_m, int l) {
    int rb = i_m * 16 + (l >> 2);
    #pragma unroll
    for (int t = 0; t < NT; ++t) {
        int c = (NB + t) * 8 + (l & 3) * 2;
        *(float2*)(d + rb * pitch + c)       = make_float2(acc[t][0], acc[t][1]);
        *(float2*)(d + (rb + 8) * pitch + c) = make_float2(acc[t][2], acc[t][3]);
    }
}

// ================= single merged prep kernel (1 block, 1024 threads) =================
__global__ void __launch_bounds__(1024, 1)
prep(const float* __restrict__ Wt1, const float* __restrict__ a11, const float* __restrict__ a21,
     const float* __restrict__ Wt2, const float* __restrict__ a12, const float* __restrict__ a22,
     const float* __restrict__ Wl, const float* __restrict__ bl,
     const float* __restrict__ g1, const float* __restrict__ b1,
     const float* __restrict__ m1, const float* __restrict__ v1,
     const float* __restrict__ g2, const float* __restrict__ b2,
     const float* __restrict__ m2, const float* __restrict__ v2)
{
    __shared__ float s_score[512];   // w1a[0..127] w1b[128..255] w2a[256..319] w2b[384..447]
    const int t = threadIdx.x;

    if (t < 512) {
        int k = t >> 2, s = t & 3;
        float sa = 0.f, sb = 0.f;
        if (k < 125) {
            #pragma unroll 4
            for (int oo = 0; oo < 16; ++oo) {
                int o = s * 16 + oo;
                float wv = Wt1[o * 125 + k];
                sa = fmaf(a11[o], wv, sa); sb = fmaf(a21[o], wv, sb);
            }
        }
        sa += __shfl_xor_sync(0xffffffffu, sa, 1); sa += __shfl_xor_sync(0xffffffffu, sa, 2);
        sb += __shfl_xor_sync(0xffffffffu, sb, 1); sb += __shfl_xor_sync(0xffffffffu, sb, 2);
        if (s == 0) { s_score[k] = sa; s_score[128 + k] = sb; }
    } else if (t < 768) {
        int k = (t - 512) >> 2, s = t & 3;
        float sa = 0.f, sb = 0.f;
        #pragma unroll
        for (int oo = 0; oo < 8; ++oo) {
            int o = s * 8 + oo;
            float wv = Wt2[o * 64 + k];
            sa = fmaf(a12[o], wv, sa); sb = fmaf(a22[o], wv, sb);
        }
        sa += __shfl_xor_sync(0xffffffffu, sa, 1); sa += __shfl_xor_sync(0xffffffffu, sa, 2);
        sb += __shfl_xor_sync(0xffffffffu, sb, 1); sb += __shfl_xor_sync(0xffffffffu, sb, 2);
        if (s == 0) { s_score[256 + k] = sa; s_score[384 + k] = sb; }
    } else if (t >= 800 && t < 805) {
        int i = t - 800;
        float s = g1[i] * rsqrtf(v1[i] + BN_EPS);
        g_CST[i] = s; g_CST[8 + i] = b1[i] - m1[i] * s;
    } else if (t >= 805 && t < 810) {
        int i = t - 805;
        float s = g2[i] * rsqrtf(v2[i] + BN_EPS);
        g_CST[16 + i] = s; g_CST[24 + i] = b2[i] - m2[i] * s;
    } else if (t >= 810 && t < 823) {
        g_CST[32 + (t - 810)] = bl[t - 810];
    }
    // Wl repack: [13 c][5 n][16 m] float4
    for (int e = t; e < 1040; e += 1024) {
        int c = e / 80, rem = e - c * 80;
        int n = rem >> 4, m = rem & 15;
        const float* wr = Wl + c * 320 + n * 64 + 2 * m;
        g_WLP4[e] = make_float4(wr[0], wr[1], wr[32], wr[33]);
    }
    __syncthreads();

    for (int e = t; e < 2304; e += 1024) {
        int T = e >> 8, q = (e >> 5) & 7, L = e & 31;
        int g = L >> 2, tt = L & 3;
        int nn = T * 8 + g;
        uint32_t v[4];
        #pragma unroll
        for (int i = 0; i < 4; ++i) {
            int k = 16 * q + (i >> 1) * 8 + (i & 1) * 4 + tt;
            float vv = 0.f;
            if (k < 125) {
                if (nn < 64)      vv = Wt1[nn * 125 + k];
                else if (nn == 64) vv = s_score[k];
                else if (nn == 65) vv = s_score[128 + k];
            }
            v[i] = f2tf32(vv);
        }
        g_W1F[e] = make_uint4(v[0], v[1], v[2], v[3]);
    }
    for (int f = t; f < 640; f += 1024) {
        int T = f >> 7, q = (f >> 5) & 3, L = f & 31;
        int g = L >> 2, tt = L & 3;
        int nn = T * 8 + g;
        uint32_t v[4];
        #pragma unroll
        for (int i = 0; i < 4; ++i) {
            int k = 16 * q + (i >> 1) * 8 + (i & 1) * 4 + tt;
            float vv = 0.f;
            if (nn < 32)      vv = Wt2[nn * 64 + k];
            else if (nn == 32) vv = s_score[256 + k];
            else if (nn == 33) vv = s_score[384 + k];
            v[i] = f2tf32(vv);
        }
        g_W2F[f] = make_uint4(v[0], v[1], v[2], v[3]);
    }
}

// ================= main fused kernel =================
__global__ void __launch_bounds__(NTHR, 4)
gat10_kernel(const float* __restrict__ x, float* __restrict__ out, int B)
{
    extern __shared__ __align__(16) char smc[];
    const int tid = threadIdx.x;
    const int w = tid >> 5, l = tid & 31;
    const int b0 = blockIdx.x * GROUP;
    float* A1 = (float*)smc;
    float* A2 = (float*)(smc + OFF_A2);

    // ---- stage x -> A1 rows (tf32, pitch 132, conflict-free) ----
    {
        const int pp = w / 5, nn = w - 5 * pp;   // row within batch = w
        const float* xrow = x + (size_t)b0 * 1250 + nn * 250 + pp * 125;
        #pragma unroll
        for (int j = 0; j < GROUP; ++j) {
            const float* src = xrow + (size_t)j * 1250;
            bool bv = (b0 + j) < B;
            float* arow = A1 + (j * 10 + w) * PITCH1;
            #pragma unroll
            for (int i = 0; i < 4; ++i) {
                int k = l + 32 * i;
                float v = (bv && k < 125) ? src[k] : 0.f;
                *(uint32_t*)(arow + k) = f2tf32(v);
            }
        }
    }
    __syncthreads();

    const int i_m = w % 5, j_n = w / 5;
    const int g = l >> 2, tt = l & 3;
    float* d1 = A1;                      // dump region aliases A1

    // ---- GEMM1: A[80x128] x W1frag[72x128] -> dump1 [80][72] ----
    {
        const float* p0 = A1 + (i_m * 16 + g) * PITCH1 + tt;
        const float* p1 = p0 + 8 * PITCH1;
        if (j_n == 0) {
            float acc[5][4];
            run_gemm<5, 0, 8>(acc, g_W1F, p0, p1, l);
            __syncthreads();
            dump_acc<5, 0>(acc, d1, PD1, i_m, l);
        } else {
            float acc[4][4];
            run_gemm<4, 5, 8>(acc, g_W1F, p0, p1, l);
            __syncthreads();
            dump_acc<4, 5>(acc, d1, PD1, i_m, l);
        }
    }
    __syncthreads();

    // ---- epilogue 1 (half-warp dual-task): warp w<8 covers batch w, path = half ----
    if (w < GROUP) {
        const int half = l >> 4, m = l & 15;     // lane m covers cols 4m..4m+3
        const int rb = w * 10 + half * 5;
        float s1[5], s2[5];
        #pragma unroll
        for (int n = 0; n < 5; ++n) {
            float2 sv = *(const float2*)(d1 + (rb + n) * PD1 + 64);
            s1[n] = sv.x; s2[n] = sv.y;
        }
        u64 oA[5], oB[5];
        #pragma unroll
        for (int n = 0; n < 5; ++n) { oA[n] = 0ull; oB[n] = 0ull; }
        #pragma unroll
        for (int j = 0; j < 5; ++j) {
            ulonglong2 hj = *(const ulonglong2*)(d1 + (rb + j) * PD1 + 4 * m);
            float e[5]; float Z = 0.f;
            #pragma unroll
            for (int i = 0; i < 5; ++i) { e[i] = __expf(lrelu(s1[i] + s2[j])); Z += e[i]; }
            float rz = __fdividef(1.f, Z);
            #pragma unroll
            for (int i = 0; i < 5; ++i) {
                float wv = e[i] * rz;
                u64 wv2 = pk2(wv, wv);
                fma2(oA[i], wv2, hj.x);
                fma2(oB[i], wv2, hj.y);
            }
        }
        #pragma unroll
        for (int i = 0; i < 5; ++i) {
            float sc = g_CST[i], bi = g_CST[8 + i];
            float2 a = upk2(oA[i]), b = upk2(oB[i]);
            uint4 pkd;
            pkd.x = f2tf32(fmaxf(fmaf(a.x, sc, bi), 0.f));
            pkd.y = f2tf32(fmaxf(fmaf(a.y, sc, bi), 0.f));
            pkd.z = f2tf32(fmaxf(fmaf(b.x, sc, bi), 0.f));
            pkd.w = f2tf32(fmaxf(fmaf(b.y, sc, bi), 0.f));
            *(uint4*)(A2 + (rb + i) * PITCH2 + 4 * m) = pkd;
        }
    }
    __syncthreads();

    // ---- GEMM2: A2[80x64] x W2frag[40x64] -> dump2 [80][40] @ region0 ----
    float* d2 = A1;
    {
        const float* p0 = A2 + (i_m * 16 + g) * PITCH2 + tt;
        const float* p1 = p0 + 8 * PITCH2;
        if (j_n == 0) {
            float acc[3][4];
            run_gemm<3, 0, 4>(acc, g_W2F, p0, p1, l);
            dump_acc<3, 0>(acc, d2, PD2, i_m, l);
        } else {
            float acc[2][4];
            run_gemm<2, 3, 4>(acc, g_W2F, p0, p1, l);
            dump_acc<2, 3>(acc, d2, PD2, i_m, l);
        }
    }
    __syncthreads();

    // ---- epilogue 2 (half-warp dual-batch): warp w<4 covers u = 2w + half ----
    if (w < 4) {
        const int half = l >> 4, m = l & 15;     // lane m covers cols 2m,2m+1
        const int u = 2 * w + half;
        const int rA = u * 10, rN = rA + 5;
        float s1a[5], s2a[5], s1b[5], s2b[5];
        #pragma unroll
        for (int n = 0; n < 5; ++n) {
            float2 sA = *(const float2*)(d2 + (rA + n) * PD2 + 32);  // (hA@a12, hA@a22)
            float2 sN = *(const float2*)(d2 + (rN + n) * PD2 + 32);  // (hN@a12, hN@a22)
            s1a[n] = sA.x; s2b[n] = sA.y;
            s1b[n] = sN.x; s2a[n] = sN.y;
        }
        u64 oA2[5], oN2[5];
        #pragma unroll
        for (int n = 0; n < 5; ++n) { oA2[n] = 0ull; oN2[n] = 0ull; }
        #pragma unroll
        for (int j = 0; j < 5; ++j) {
            u64 hAj = *(const u64*)(d2 + (rA + j) * PD2 + 2 * m);
            u64 hNj = *(const u64*)(d2 + (rN + j) * PD2 + 2 * m);
            float eA[5], eN[5]; float ZA = 0.f, ZN = 0.f;
            #pragma unroll
            for (int i = 0; i < 5; ++i) {
                eA[i] = __expf(lrelu(s1a[i] + s2a[j])); ZA += eA[i];
                eN[i] = __expf(lrelu(s1b[i] + s2b[j])); ZN += eN[i];
            }
            float rzA = __fdividef(1.f, ZA), rzN = __fdividef(1.f, ZN);
            #pragma unroll
            for (int i = 0; i < 5; ++i) {
                float wa = eA[i] * rzA, wn = eN[i] * rzN;
                fma2(oA2[i], pk2(wa, wa), hAj);
                fma2(oN2[i], pk2(wn, wn), hNj);
            }
        }
        // BN2 + ReLU -> packed feature pairs
        u64 fa2[5], fb2[5];
        #pragma unroll
        for (int n = 0; n < 5; ++n) {
            float sc = g_CST[16 + n], bi = g_CST[24 + n];
            float2 a = upk2(oA2[n]), b = upk2(oN2[n]);
            fa2[n] = pk2(fmaxf(fmaf(a.x, sc, bi), 0.f), fmaxf(fmaf(a.y, sc, bi), 0.f));
            fb2[n] = pk2(fmaxf(fmaf(b.x, sc, bi), 0.f), fmaxf(fmaf(b.y, sc, bi), 0.f));
        }
        // final linear: packed fma, 16-lane reduce per half
        const ulonglong2* WLP = (const ulonglong2*)g_WLP4;
        float ov = 0.f;
        #pragma unroll
        for (int c = 0; c < 13; ++c) {
            u64 a2 = 0ull;
            #pragma unroll
            for (int n = 0; n < 5; ++n) {
                ulonglong2 wl = WLP[(c * 5 + n) * 16 + m];
                fma2(a2, fa2[n], wl.x);
                fma2(a2, fb2[n], wl.y);
            }
            float2 p = upk2(a2);
            float v = p.x + p.y;
            v += __shfl_xor_sync(0xffffffffu, v, 8);
            v += __shfl_xor_sync(0xffffffffu, v, 4);
            v += __shfl_xor_sync(0xffffffffu, v, 2);
            v += __shfl_xor_sync(0xffffffffu, v, 1);
            if (m == c) ov = v;
        }
        int bb = b0 + u;
        if (m < 13 && bb < B)
            out[(size_t)bb * 13 + m] = ov + g_CST[32 + m];
    }
}

extern "C" void kernel_launch(void* const* d_in, const int* in_sizes, int n_in,
                              void* d_out, int out_size)
{
    const float* x   = (const float*)d_in[0];
    const float* Wt1 = (const float*)d_in[1];
    const float* a11 = (const float*)d_in[2];
    const float* a21 = (const float*)d_in[3];
    const float* g1  = (const float*)d_in[4];
    const float* b1  = (const float*)d_in[5];
    const float* m1  = (const float*)d_in[6];
    const float* v1  = (const float*)d_in[7];
    const float* Wt2 = (const float*)d_in[8];
    const float* a12 = (const float*)d_in[9];
    const float* a22 = (const float*)d_in[10];
    const float* g2  = (const float*)d_in[11];
    const float* b2  = (const float*)d_in[12];
    const float* m2  = (const float*)d_in[13];
    const float* v2  = (const float*)d_in[14];
    const float* Wl  = (const float*)d_in[15];
    const float* bl  = (const float*)d_in[16];

    int B = in_sizes[0] / 1250;
    prep<<<1, 1024>>>(Wt1, a11, a21, Wt2, a12, a22, Wl, bl,
                      g1, b1, m1, v1, g2, b2, m2, v2);
    int grid = (B + GROUP - 1) / GROUP;
    cudaFuncSetAttribute(gat10_kernel, cudaFuncAttributeMaxDynamicSharedMemorySize, SMEM_BYTES);
    cudaFuncSetAttribute(gat10_kernel, cudaFuncAttributePreferredSharedMemoryCarveout, 100);
    gat10_kernel<<<grid, NTHR, SMEM_BYTES>>>(x, (float*)d_out, B);
}

// round 11
// speedup vs baseline: 1.9312x; 1.2132x over previous
#include <cuda_runtime.h>
#include <cstdint>

#define NTHR 256
#define NW 8
#define GROUP 12
#define ALPHA 0.2f
#define BN_EPS 1e-5f

// ---- smem layout (bytes) ----
// A1 [128][132 f32] = 67584 @0 (120 rows used; dead after GEMM1 dump)
// dump1 [128][72] f32 = 36864 @0        (aliases A1)
// A2   [128][68] f32  = 34816 @36864    (aliases dead A1 tail)
// dump2 [128][40] f32 = 20480 @0        (aliases dump1, dead after epi1)
#define OFF_A2 36864
#define SMEM_BYTES 71680
#define PITCH1 132
#define PITCH2 68
#define PD1 72
#define PD2 40

typedef unsigned long long u64;

// ---- device-global prepared weights ----
__device__ uint4  g_W1F[2304];   // [9 ntile][8 q(k16)][32 lane] {b0e,b1e,b0o,b1o} tf32
__device__ uint4  g_W2F[640];    // [5][4][32]
__device__ float4 g_WLP4[1040];  // [13 c][5 n][16 m]
__device__ float  g_CST[64];     // sc1@0 bi1@8 sc2@16 bi2@24 bl@32

// ------------- helpers -------------
__device__ __forceinline__ uint32_t f2tf32(float v) {
    uint32_t r; asm("cvt.rna.tf32.f32 %0, %1;" : "=r"(r) : "f"(v)); return r;
}
__device__ __forceinline__ void mma_tf32(float* d, const uint32_t* a, uint32_t b0, uint32_t b1) {
    asm volatile("mma.sync.aligned.m16n8k8.row.col.f32.tf32.tf32.f32 "
                 "{%0,%1,%2,%3},{%4,%5,%6,%7},{%8,%9},{%0,%1,%2,%3};"
                 : "+f"(d[0]), "+f"(d[1]), "+f"(d[2]), "+f"(d[3])
                 : "r"(a[0]), "r"(a[1]), "r"(a[2]), "r"(a[3]), "r"(b0), "r"(b1));
}
__device__ __forceinline__ u64 pk2(float a, float b) {
    u64 r; asm("mov.b64 %0, {%1, %2};" : "=l"(r) : "f"(a), "f"(b)); return r;
}
__device__ __forceinline__ float2 upk2(u64 v) {
    float2 r; asm("mov.b64 {%0, %1}, %2;" : "=f"(r.x), "=f"(r.y) : "l"(v)); return r;
}
__device__ __forceinline__ void fma2(u64& d, u64 a, u64 b) {
    asm("fma.rn.f32x2 %0, %1, %2, %3;" : "=l"(d) : "l"(a), "l"(b), "l"(d));
}
__device__ __forceinline__ float lrelu(float v) { return v > 0.f ? v : ALPHA * v; }

// dual-m-tile tf32 GEMM: A from smem rows (conflict-free LDS.32), B frags from global (L1-hot)
template<int NT, int NB, int NQ>
__device__ __forceinline__ void run_gemm2(float (&acc)[2][NT][4], const uint4* __restrict__ WF,
                                          const float* __restrict__ p00, const float* __restrict__ p01,
                                          const float* __restrict__ p10, const float* __restrict__ p11,
                                          int l) {
    #pragma unroll
    for (int mm = 0; mm < 2; ++mm)
        #pragma unroll
        for (int t = 0; t < NT; ++t) { acc[mm][t][0]=0.f; acc[mm][t][1]=0.f; acc[mm][t][2]=0.f; acc[mm][t][3]=0.f; }
    #pragma unroll
    for (int q = 0; q < NQ; ++q) {
        const int k0 = 16 * q;
        uint32_t aE0[4], aO0[4], aE1[4], aO1[4];
        aE0[0] = __float_as_uint(p00[k0]);      aE0[1] = __float_as_uint(p01[k0]);
        aE0[2] = __float_as_uint(p00[k0 + 4]);  aE0[3] = __float_as_uint(p01[k0 + 4]);
        aO0[0] = __float_as_uint(p00[k0 + 8]);  aO0[1] = __float_as_uint(p01[k0 + 8]);
        aO0[2] = __float_as_uint(p00[k0 + 12]); aO0[3] = __float_as_uint(p01[k0 + 12]);
        aE1[0] = __float_as_uint(p10[k0]);      aE1[1] = __float_as_uint(p11[k0]);
        aE1[2] = __float_as_uint(p10[k0 + 4]);  aE1[3] = __float_as_uint(p11[k0 + 4]);
        aO1[0] = __float_as_uint(p10[k0 + 8]);  aO1[1] = __float_as_uint(p11[k0 + 8]);
        aO1[2] = __float_as_uint(p10[k0 + 12]); aO1[3] = __float_as_uint(p11[k0 + 12]);
        #pragma unroll
        for (int t = 0; t < NT; ++t) {
            uint4 bf = WF[((NB + t) * NQ + q) * 32 + l];
            mma_tf32(acc[0][t], aE0, bf.x, bf.y);
            mma_tf32(acc[0][t], aO0, bf.z, bf.w);
            mma_tf32(acc[1][t], aE1, bf.x, bf.y);
            mma_tf32(acc[1][t], aO1, bf.z, bf.w);
        }
    }
}
template<int NT, int NB>
__device__ __forceinline__ void dump_acc2(const float (&acc)[2][NT][4], float* d, int pitch, int i_m, int l) {
    #pragma unroll
    for (int mm = 0; mm < 2; ++mm) {
        int rb = (i_m + 4 * mm) * 16 + (l >> 2);
        #pragma unroll
        for (int t = 0; t < NT; ++t) {
            int c = (NB + t) * 8 + (l & 3) * 2;
            *(float2*)(d + rb * pitch + c)       = make_float2(acc[mm][t][0], acc[mm][t][1]);
            *(float2*)(d + (rb + 8) * pitch + c) = make_float2(acc[mm][t][2], acc[mm][t][3]);
        }
    }
}

// ================= single merged prep kernel (1 block, 1024 threads) =================
__global__ void __launch_bounds__(1024, 1)
prep(const float* __restrict__ Wt1, const float* __restrict__ a11, const float* __restrict__ a21,
     const float* __restrict__ Wt2, const float* __restrict__ a12, const float* __restrict__ a22,
     const float* __restrict__ Wl, const float* __restrict__ bl,
     const float* __restrict__ g1, const float* __restrict__ b1,
     const float* __restrict__ m1, const float* __restrict__ v1,
     const float* __restrict__ g2, const float* __restrict__ b2,
     const float* __restrict__ m2, const float* __restrict__ v2)
{
    __shared__ float s_score[512];
    const int t = threadIdx.x;

    if (t < 512) {
        int k = t >> 2, s = t & 3;
        float sa = 0.f, sb = 0.f;
        if (k < 125) {
            #pragma unroll 4
            for (int oo = 0; oo < 16; ++oo) {
                int o = s * 16 + oo;
                float wv = Wt1[o * 125 + k];
                sa = fmaf(a11[o], wv, sa); sb = fmaf(a21[o], wv, sb);
            }
        }
        sa += __shfl_xor_sync(0xffffffffu, sa, 1); sa += __shfl_xor_sync(0xffffffffu, sa, 2);
        sb += __shfl_xor_sync(0xffffffffu, sb, 1); sb += __shfl_xor_sync(0xffffffffu, sb, 2);
        if (s == 0) { s_score[k] = sa; s_score[128 + k] = sb; }
    } else if (t < 768) {
        int k = (t - 512) >> 2, s = t & 3;
        float sa = 0.f, sb = 0.f;
        #pragma unroll
        for (int oo = 0; oo < 8; ++oo) {
            int o = s * 8 + oo;
            float wv = Wt2[o * 64 + k];
            sa = fmaf(a12[o], wv, sa); sb = fmaf(a22[o], wv, sb);
        }
        sa += __shfl_xor_sync(0xffffffffu, sa, 1); sa += __shfl_xor_sync(0xffffffffu, sa, 2);
        sb += __shfl_xor_sync(0xffffffffu, sb, 1); sb += __shfl_xor_sync(0xffffffffu, sb, 2);
        if (s == 0) { s_score[256 + k] = sa; s_score[384 + k] = sb; }
    } else if (t >= 800 && t < 805) {
        int i = t - 800;
        float s = g1[i] * rsqrtf(v1[i] + BN_EPS);
        g_CST[i] = s; g_CST[8 + i] = b1[i] - m1[i] * s;
    } else if (t >= 805 && t < 810) {
        int i = t - 805;
        float s = g2[i] * rsqrtf(v2[i] + BN_EPS);
        g_CST[16 + i] = s; g_CST[24 + i] = b2[i] - m2[i] * s;
    } else if (t >= 810 && t < 823) {
        g_CST[32 + (t - 810)] = bl[t - 810];
    }
    for (int e = t; e < 1040; e += 1024) {
        int c = e / 80, rem = e - c * 80;
        int n = rem >> 4, m = rem & 15;
        const float* wr = Wl + c * 320 + n * 64 + 2 * m;
        g_WLP4[e] = make_float4(wr[0], wr[1], wr[32], wr[33]);
    }
    __syncthreads();

    for (int e = t; e < 2304; e += 1024) {
        int T = e >> 8, q = (e >> 5) & 7, L = e & 31;
        int g = L >> 2, tt = L & 3;
        int nn = T * 8 + g;
        uint32_t v[4];
        #pragma unroll
        for (int i = 0; i < 4; ++i) {
            int k = 16 * q + (i >> 1) * 8 + (i & 1) * 4 + tt;
            float vv = 0.f;
            if (k < 125) {
                if (nn < 64)      vv = Wt1[nn * 125 + k];
                else if (nn == 64) vv = s_score[k];
                else if (nn == 65) vv = s_score[128 + k];
            }
            v[i] = f2tf32(vv);
        }
        g_W1F[e] = make_uint4(v[0], v[1], v[2], v[3]);
    }
    for (int f = t; f < 640; f += 1024) {
        int T = f >> 7, q = (f >> 5) & 3, L = f & 31;
        int g = L >> 2, tt = L & 3;
        int nn = T * 8 + g;
        uint32_t v[4];
        #pragma unroll
        for (int i = 0; i < 4; ++i) {
            int k = 16 * q + (i >> 1) * 8 + (i & 1) * 4 + tt;
            float vv = 0.f;
            if (nn < 32)      vv = Wt2[nn * 64 + k];
            else if (nn == 32) vv = s_score[256 + k];
            else if (nn == 33) vv = s_score[384 + k];
            v[i] = f2tf32(vv);
        }
        g_W2F[f] = make_uint4(v[0], v[1], v[2], v[3]);
    }
}

// ================= main fused kernel =================
__global__ void __launch_bounds__(NTHR, 3)
gat11_kernel(const float* __restrict__ x, float* __restrict__ out, int B)
{
    extern __shared__ __align__(16) char smc[];
    const int tid = threadIdx.x;
    const int w = tid >> 5, l = tid & 31;
    const int b0 = blockIdx.x * GROUP;
    float* A1 = (float*)smc;
    float* A2 = (float*)(smc + OFF_A2);

    // ---- stage x -> A1 rows 0..127 (tf32, pitch 132, conflict-free; rows>=120 zero) ----
    {
        #pragma unroll
        for (int j = 0; j < 16; ++j) {
            int r = j * NW + w;
            int lb = r / 10, rem = r - lb * 10;
            int p = rem / 5, n = rem - p * 5;
            bool rv = (r < 120) && (b0 + lb < B);
            const float* src = x + (size_t)(b0 + lb) * 1250 + n * 250 + p * 125;
            float* arow = A1 + r * PITCH1;
            #pragma unroll
            for (int i = 0; i < 4; ++i) {
                int k = l + 32 * i;
                float v = (rv && k < 125) ? src[k] : 0.f;
                *(uint32_t*)(arow + k) = f2tf32(v);
            }
        }
    }
    __syncthreads();

    const int i_m = w & 3, j_n = w >> 2;
    const int g = l >> 2, tt = l & 3;
    float* d1 = A1;                      // dump region aliases A1

    // ---- GEMM1: A[128x128] x W1frag[72x128] -> dump1 [128][72], m-tile pairs ----
    {
        const float* p00 = A1 + (i_m * 16 + g) * PITCH1 + tt;
        const float* p01 = p00 + 8 * PITCH1;
        const float* p10 = A1 + ((i_m + 4) * 16 + g) * PITCH1 + tt;
        const float* p11 = p10 + 8 * PITCH1;
        if (j_n == 0) {
            float acc[2][5][4];
            run_gemm2<5, 0, 8>(acc, g_W1F, p00, p01, p10, p11, l);
            __syncthreads();
            dump_acc2<5, 0>(acc, d1, PD1, i_m, l);
        } else {
            float acc[2][4][4];
            run_gemm2<4, 5, 8>(acc, g_W1F, p00, p01, p10, p11, l);
            __syncthreads();
            dump_acc2<4, 5>(acc, d1, PD1, i_m, l);
        }
    }
    __syncthreads();

    // ---- epilogue 1 (half-warp dual-path): warp covers batches {w, w+8} ----
    for (int u = w; u < GROUP; u += NW) {
        const int half = l >> 4, m = l & 15;     // lane m covers cols 4m..4m+3
        const int rb = u * 10 + half * 5;
        float s1[5], s2[5];
        #pragma unroll
        for (int n = 0; n < 5; ++n) {
            float2 sv = *(const float2*)(d1 + (rb + n) * PD1 + 64);
            s1[n] = sv.x; s2[n] = sv.y;
        }
        u64 oA[5], oB[5];
        #pragma unroll
        for (int n = 0; n < 5; ++n) { oA[n] = 0ull; oB[n] = 0ull; }
        #pragma unroll
        for (int j = 0; j < 5; ++j) {
            ulonglong2 hj = *(const ulonglong2*)(d1 + (rb + j) * PD1 + 4 * m);
            float e[5]; float Z = 0.f;
            #pragma unroll
            for (int i = 0; i < 5; ++i) { e[i] = __expf(lrelu(s1[i] + s2[j])); Z += e[i]; }
            float rz = __fdividef(1.f, Z);
            #pragma unroll
            for (int i = 0; i < 5; ++i) {
                float wv = e[i] * rz;
                u64 wv2 = pk2(wv, wv);
                fma2(oA[i], wv2, hj.x);
                fma2(oB[i], wv2, hj.y);
            }
        }
        #pragma unroll
        for (int i = 0; i < 5; ++i) {
            float sc = g_CST[i], bi = g_CST[8 + i];
            float2 a = upk2(oA[i]), b = upk2(oB[i]);
            uint4 pkd;
            pkd.x = f2tf32(fmaxf(fmaf(a.x, sc, bi), 0.f));
            pkd.y = f2tf32(fmaxf(fmaf(a.y, sc, bi), 0.f));
            pkd.z = f2tf32(fmaxf(fmaf(b.x, sc, bi), 0.f));
            pkd.w = f2tf32(fmaxf(fmaf(b.y, sc, bi), 0.f));
            *(uint4*)(A2 + (rb + i) * PITCH2 + 4 * m) = pkd;
        }
    }
    // zero-pad A2 rows 120..127 (GEMM2 reads them; avoid stale tf32 garbage)
    {
        int r = 120 + w;
        float* arow = A2 + r * PITCH2;
        *(uint2*)(arow + 2 * l) = make_uint2(0u, 0u);
    }
    __syncthreads();

    // ---- GEMM2: A2[128x64] x W2frag[40x64] -> dump2 [128][40] @ region0 ----
    float* d2 = A1;
    {
        const float* p00 = A2 + (i_m * 16 + g) * PITCH2 + tt;
        const float* p01 = p00 + 8 * PITCH2;
        const float* p10 = A2 + ((i_m + 4) * 16 + g) * PITCH2 + tt;
        const float* p11 = p10 + 8 * PITCH2;
        if (j_n == 0) {
            float acc[2][3][4];
            run_gemm2<3, 0, 4>(acc, g_W2F, p00, p01, p10, p11, l);
            dump_acc2<3, 0>(acc, d2, PD2, i_m, l);
        } else {
            float acc[2][2][4];
            run_gemm2<2, 3, 4>(acc, g_W2F, p00, p01, p10, p11, l);
            dump_acc2<2, 3>(acc, d2, PD2, i_m, l);
        }
    }
    __syncthreads();

    // ---- epilogue 2 (half-warp dual-batch): warps 0..5 cover u = 2w + half ----
    if (w < 6) {
        const int half = l >> 4, m = l & 15;     // lane m covers cols 2m,2m+1
        const int u = 2 * w + half;
        const int rA = u * 10, rN = rA + 5;
        float s1a[5], s2a[5], s1b[5], s2b[5];
        #pragma unroll
        for (int n = 0; n < 5; ++n) {
            float2 sA = *(const float2*)(d2 + (rA + n) * PD2 + 32);  // (hA@a12, hA@a22)
            float2 sN = *(const float2*)(d2 + (rN + n) * PD2 + 32);  // (hN@a12, hN@a22)
            s1a[n] = sA.x; s2b[n] = sA.y;
            s1b[n] = sN.x; s2a[n] = sN.y;
        }
        u64 oA2[5], oN2[5];
        #pragma unroll
        for (int n = 0; n < 5; ++n) { oA2[n] = 0ull; oN2[n] = 0ull; }
        #pragma unroll
        for (int j = 0; j < 5; ++j) {
            u64 hAj = *(const u64*)(d2 + (rA + j) * PD2 + 2 * m);
            u64 hNj = *(const u64*)(d2 + (rN + j) * PD2 + 2 * m);
            float eA[5], eN[5]; float ZA = 0.f, ZN = 0.f;
            #pragma unroll
            for (int i = 0; i < 5; ++i) {
                eA[i] = __expf(lrelu(s1a[i] + s2a[j])); ZA += eA[i];
                eN[i] = __expf(lrelu(s1b[i] + s2b[j])); ZN += eN[i];
            }
            float rzA = __fdividef(1.f, ZA), rzN = __fdividef(1.f, ZN);
            #pragma unroll
            for (int i = 0; i < 5; ++i) {
                float wa = eA[i] * rzA, wn = eN[i] * rzN;
                fma2(oA2[i], pk2(wa, wa), hAj);
                fma2(oN2[i], pk2(wn, wn), hNj);
            }
        }
        u64 fa2[5], fb2[5];
        #pragma unroll
        for (int n = 0; n < 5; ++n) {
            float sc = g_CST[16 + n], bi = g_CST[24 + n];
            float2 a = upk2(oA2[n]), b = upk2(oN2[n]);
            fa2[n] = pk2(fmaxf(fmaf(a.x, sc, bi), 0.f), fmaxf(fmaf(a.y, sc, bi), 0.f));
            fb2[n] = pk2(fmaxf(fmaf(b.x, sc, bi), 0.f), fmaxf(fmaf(b.y, sc, bi), 0.f));
        }
        const ulonglong2* WLP = (const ulonglong2*)g_WLP4;
        float ov = 0.f;
        #pragma unroll
        for (int c = 0; c < 13; ++c) {
            u64 a2 = 0ull;
            #pragma unroll
            for (int n = 0; n < 5; ++n) {
                ulonglong2 wl = WLP[(c * 5 + n) * 16 + m];
                fma2(a2, fa2[n], wl.x);
                fma2(a2, fb2[n], wl.y);
            }
            float2 p = upk2(a2);
            float v = p.x + p.y;
            v += __shfl_xor_sync(0xffffffffu, v, 8);
            v += __shfl_xor_sync(0xffffffffu, v, 4);
            v += __shfl_xor_sync(0xffffffffu, v, 2);
            v += __shfl_xor_sync(0xffffffffu, v, 1);
            if (m == c) ov = v;
        }
        int bb = b0 + u;
        if (m < 13 && bb < B)
            out[(size_t)bb * 13 + m] = ov + g_CST[32 + m];
    }
}

extern "C" void kernel_launch(void* const* d_in, const int* in_sizes, int n_in,
                              void* d_out, int out_size)
{
    const float* x   = (const float*)d_in[0];
    const float* Wt1 = (const float*)d_in[1];
    const float* a11 = (const float*)d_in[2];
    const float* a21 = (const float*)d_in[3];
    const float* g1  = (const float*)d_in[4];
    const float* b1  = (const float*)d_in[5];
    const float* m1  = (const float*)d_in[6];
    const float* v1  = (const float*)d_in[7];
    const float* Wt2 = (const float*)d_in[8];
    const float* a12 = (const float*)d_in[9];
    const float* a22 = (const float*)d_in[10];
    const float* g2  = (const float*)d_in[11];
    const float* b2  = (const float*)d_in[12];
    const float* m2  = (const float*)d_in[13];
    const float* v2  = (const float*)d_in[14];
    const float* Wl  = (const float*)d_in[15];
    const float* bl  = (const float*)d_in[16];

    int B = in_sizes[0] / 1250;
    prep<<<1, 1024>>>(Wt1, a11, a21, Wt2, a12, a22, Wl, bl,
                      g1, b1, m1, v1, g2, b2, m2, v2);
    int grid = (B + GROUP - 1) / GROUP;
    cudaFuncSetAttribute(gat11_kernel, cudaFuncAttributeMaxDynamicSharedMemorySize, SMEM_BYTES);
    cudaFuncSetAttribute(gat11_kernel, cudaFuncAttributePreferredSharedMemoryCarveout, 100);
    gat11_kernel<<<grid, NTHR, SMEM_BYTES>>>(x, (float*)d_out, B);
}